// round 4
// baseline (speedup 1.0000x reference)
#include <cuda_runtime.h>
#include <cstdint>
#include <math.h>

// Problem constants
constexpr int Bn    = 4;
constexpr int Sn    = 4096;
constexpr int DIMn  = 1024;
constexpr int SDIMn = 256;
constexpr int Mn    = Bn * Sn;          // 16384 tokens
constexpr int TCH   = 32;               // scan chunk length
constexpr int NCH   = Sn / TCH;         // 128 chunks per sequence
constexpr int NBIG  = 2816;             // fused projection width

// column offsets inside the fused output [M, 2816]
constexpr int COL_U    = 0;      // tanh    (Wi)
constexpr int COL_G    = 1024;   // sigmoid (Wg)
constexpr int COL_XS   = 2048;   // tanh    (Wsin)
constexpr int COL_DEC  = 2304;   // sigmoid (Wd)
constexpr int COL_SEL  = 2560;   // sigmoid (Wsel)

// ---------------- scratch (device globals; no allocations) ----------------
__device__ __align__(16) float g_h    [(size_t)Mn * DIMn];   // LN out, later z
__device__ __align__(16) float g_mixed[(size_t)Mn * DIMn];
__device__ __align__(16) float g_mx   [(size_t)Mn * NBIG];   // fused proj out
__device__ __align__(16) float g_st   [(size_t)Mn * SDIMn];  // round(sel*state)
__device__ __align__(16) float g_chA  [Bn * NCH * SDIMn];
__device__ __align__(16) float g_chB  [Bn * NCH * SDIMn];
__device__ __align__(16) float g_chS0 [Bn * NCH * SDIMn];
__device__ __align__(16) float g_bias [NBIG];

// transposed (tf32-rounded) weights, packed [n][k]
// big block: rows 0..2815 all with K=1024 (Wi|Wg|Wsin|Wd|Wsel)
constexpr size_t OFFB_WI   = 0;
constexpr size_t OFFB_WG   = (size_t)1024 * 1024;
constexpr size_t OFFB_WSIN = (size_t)2048 * 1024;
constexpr size_t OFFB_WD   = (size_t)2304 * 1024;
constexpr size_t OFFB_WSEL = (size_t)2560 * 1024;
constexpr size_t OFF_WSO   = (size_t)2816 * 1024;            // 1024 rows x K=256
constexpr size_t OFF_WOUT  = OFF_WSO + (size_t)1024 * 256;   // 1024 rows x K=1024
__device__ __align__(16) float g_wT[OFF_WOUT + (size_t)1024 * 1024];

// ---------------- helpers ----------------
__device__ __forceinline__ float tf32rna(float v) {
    uint32_t u;
    asm("cvt.rna.tf32.f32 %0, %1;" : "=r"(u) : "f"(v));
    return __uint_as_float(u);
}
__device__ __forceinline__ uint32_t smem_u32(const void* p) {
    uint32_t a;
    asm("{ .reg .u64 t; cvta.to.shared.u64 t, %1; cvt.u32.u64 %0, t; }"
        : "=r"(a) : "l"(p));
    return a;
}
__device__ __forceinline__ void cpa16(uint32_t s, const void* g) {
    asm volatile("cp.async.cg.shared.global [%0], [%1], 16;" :: "r"(s), "l"(g));
}
__device__ __forceinline__ void ldsm4(uint32_t* r, uint32_t addr) {
    asm volatile("ldmatrix.sync.aligned.m8n8.x4.shared.b16 {%0,%1,%2,%3}, [%4];"
                 : "=r"(r[0]), "=r"(r[1]), "=r"(r[2]), "=r"(r[3]) : "r"(addr));
}
__device__ __forceinline__ void mma8(float* d, const uint32_t* a, const uint32_t* b) {
    asm volatile(
        "mma.sync.aligned.m16n8k8.row.col.f32.tf32.tf32.f32 "
        "{%0,%1,%2,%3}, {%4,%5,%6,%7}, {%8,%9}, {%0,%1,%2,%3};"
        : "+f"(d[0]), "+f"(d[1]), "+f"(d[2]), "+f"(d[3])
        : "r"(a[0]), "r"(a[1]), "r"(a[2]), "r"(a[3]), "r"(b[0]), "r"(b[1]));
}

// ---------------- LayerNorm ----------------
__global__ void ln_kernel(const float* __restrict__ x,
                          const float* __restrict__ gw,
                          const float* __restrict__ bw) {
    const int row = blockIdx.x;
    const int t   = threadIdx.x;
    const float* xr = x + (size_t)row * DIMn;

    float4 v = *(const float4*)(xr + t * 4);
    float s  = v.x + v.y + v.z + v.w;
    float s2 = fmaf(v.x, v.x, fmaf(v.y, v.y, fmaf(v.z, v.z, v.w * v.w)));
    #pragma unroll
    for (int o = 16; o > 0; o >>= 1) {
        s  += __shfl_xor_sync(0xffffffffu, s,  o);
        s2 += __shfl_xor_sync(0xffffffffu, s2, o);
    }
    __shared__ float ws[8], ws2[8];
    __shared__ float s_mu, s_rs;
    const int warp = t >> 5, lane = t & 31;
    if (lane == 0) { ws[warp] = s; ws2[warp] = s2; }
    __syncthreads();
    if (t == 0) {
        float a = 0.f, b = 0.f;
        #pragma unroll
        for (int i = 0; i < 8; i++) { a += ws[i]; b += ws2[i]; }
        float mu  = a * (1.0f / DIMn);
        float var = b * (1.0f / DIMn) - mu * mu;
        s_mu = mu; s_rs = rsqrtf(var + 1e-5f);
    }
    __syncthreads();
    const float mu = s_mu, rs = s_rs;
    float4 g4 = *(const float4*)(gw + t * 4);
    float4 b4 = *(const float4*)(bw + t * 4);
    float4 o;
    o.x = (v.x - mu) * rs * g4.x + b4.x;
    o.y = (v.y - mu) * rs * g4.y + b4.y;
    o.z = (v.z - mu) * rs * g4.z + b4.z;
    o.w = (v.w - mu) * rs * g4.w + b4.w;
    *(float4*)(g_h + (size_t)row * DIMn + t * 4) = o;
}

// ---------------- depthwise conv1d (output tf32-rounded) ----------------
__global__ void conv_kernel(const float* __restrict__ mw,
                            const float* __restrict__ mb) {
    const int idx = blockIdx.x * blockDim.x + threadIdx.x;
    constexpr int D4 = DIMn / 4;
    if (idx >= Mn * D4) return;
    const int m = idx / D4;
    const int d = (idx - m * D4) * 4;
    const int s = m % Sn;

    const float4 c = *(const float4*)(g_h + (size_t)m * DIMn + d);
    float4 l = make_float4(0.f, 0.f, 0.f, 0.f);
    float4 r = make_float4(0.f, 0.f, 0.f, 0.f);
    if (s > 0)      l = *(const float4*)(g_h + (size_t)(m - 1) * DIMn + d);
    if (s < Sn - 1) r = *(const float4*)(g_h + (size_t)(m + 1) * DIMn + d);

    const float* lc = (const float*)&l;
    const float* cc = (const float*)&c;
    const float* rc = (const float*)&r;
    float4 out; float* oc = (float*)&out;
    #pragma unroll
    for (int j = 0; j < 4; j++) {
        const float w0 = __ldg(mw + (d + j) * 3 + 0);
        const float w1 = __ldg(mw + (d + j) * 3 + 1);
        const float w2 = __ldg(mw + (d + j) * 3 + 2);
        oc[j] = tf32rna(fmaf(w0, lc[j], fmaf(w1, cc[j],
                         fmaf(w2, rc[j], __ldg(mb + d + j)))));
    }
    *(float4*)(g_mixed + (size_t)m * DIMn + d) = out;
}

// ---------------- chunked scan (reads from fused buffer g_mx) ----------------
__global__ void scan_p1() {
    const int b = blockIdx.y, c = blockIdx.x, n = threadIdx.x;
    const size_t row0 = (size_t)(b * Sn + c * TCH);
    float A = 1.f, st = 0.f;
    #pragma unroll
    for (int t = 0; t < TCH; t++) {
        const size_t rb = (row0 + t) * NBIG;
        const float d  = g_mx[rb + COL_DEC + n];
        const float xv = g_mx[rb + COL_XS  + n];
        A *= d;
        st = fmaf(d, st, (1.f - d) * xv);
    }
    const int o = (b * NCH + c) * SDIMn + n;
    g_chA[o] = A; g_chB[o] = st;
}
__global__ void scan_p2() {
    const int b = blockIdx.x, n = threadIdx.x;
    float s = 0.f;
    #pragma unroll 4
    for (int c = 0; c < NCH; c++) {
        const int o = (b * NCH + c) * SDIMn + n;
        g_chS0[o] = s;
        s = fmaf(g_chA[o], s, g_chB[o]);
    }
}
__global__ void scan_p3() {
    const int b = blockIdx.y, c = blockIdx.x, n = threadIdx.x;
    const size_t row0 = (size_t)(b * Sn + c * TCH);
    float st = g_chS0[(b * NCH + c) * SDIMn + n];
    #pragma unroll
    for (int t = 0; t < TCH; t++) {
        const size_t rb = (row0 + t) * NBIG;
        const float d  = g_mx[rb + COL_DEC + n];
        const float xv = g_mx[rb + COL_XS  + n];
        st = fmaf(d, st, (1.f - d) * xv);
        const float sl = g_mx[rb + COL_SEL + n];
        g_st[(row0 + t) * SDIMn + n] = tf32rna(sl * st);
    }
}

// ---------------- weight transpose + tf32 round: Wt[n][k] = rna(W[k][n]) ----
__global__ void transpose_kernel(const float* __restrict__ in,
                                 float* __restrict__ out, int K, int N) {
    __shared__ float tile[32][33];
    const int n0 = blockIdx.x * 32, k0 = blockIdx.y * 32;
    const int tx = threadIdx.x, ty = threadIdx.y;   // 32 x 8
    #pragma unroll
    for (int j = 0; j < 32; j += 8)
        tile[ty + j][tx] = in[(size_t)(k0 + ty + j) * N + n0 + tx];
    __syncthreads();
    #pragma unroll
    for (int j = 0; j < 32; j += 8)
        out[(size_t)(n0 + ty + j) * K + k0 + tx] = tf32rna(tile[tx][ty + j]);
}

// ---------------- pack fused bias vector ----------------
__global__ void pack_bias(const float* __restrict__ bi, const float* __restrict__ bg,
                          const float* __restrict__ bsin, const float* __restrict__ bd,
                          const float* __restrict__ bsel) {
    const int t = blockIdx.x * 256 + threadIdx.x;
    if (t >= NBIG) return;
    float v;
    if (t < 1024)      v = bi[t];
    else if (t < 2048) v = bg[t - 1024];
    else if (t < 2304) v = bsin[t - 2048];
    else if (t < 2560) v = bd[t - 2304];
    else               v = bsel[t - 2560];
    g_bias[t] = v;
}

// ---------------- big-tile tf32 mma GEMM ----------------
// 256x128 CTA tile, 8 warps (4x2) of 64x64, K-chunk 8, 5-stage cp.async.
// C[M,N] = epi( A[M,K] @ Bt[N,K]^T + bias[col] )
// EPI 0: per-column act (tanh / sigmoid per fused layout), C stride ldc
// EPI 1: round( g*v + (1-g)*u ), g=e1, u=e2 (stride lde)
// EPI 2: v + x (e1, stride lde)
constexpr int SPAD    = 12;                 // floats per smem row (8 data + 4 pad)
constexpr int STG_FL  = 384 * SPAD;         // floats per stage (A 256 + B 128 rows)
constexpr int STAGES  = 5;
constexpr int SMEM_BYTES = STAGES * STG_FL * 4;   // 92160

template <int EPI>
__global__ void __launch_bounds__(256, 1)
mma2(const float* __restrict__ A, const float* __restrict__ Bt,
     const float* __restrict__ bias, float* __restrict__ C,
     const float* __restrict__ e1, const float* __restrict__ e2,
     int K, int ldc, int lde) {
    extern __shared__ float smc[];
    const int tid  = threadIdx.x;
    const int wid  = tid >> 5, lane = tid & 31;
    const int wm   = wid >> 1, wn = wid & 1;     // warp grid 4x2
    const int bm   = blockIdx.y * 256;
    const int bn   = blockIdx.x * 128;
    const uint32_t smemBase = smem_u32(smc);

    // cp.async coords: A row = tid (2 chunks), B row = tid/2 (1 chunk)
    const int arow  = tid;
    const int brow  = tid >> 1;
    const int bhalf = tid & 1;

    // ldmatrix lane offsets (bytes rel. to stage base)
    uint32_t offA[4], offB[4];
    {
        const int blk = lane >> 3, rIn = lane & 7;
        #pragma unroll
        for (int i = 0; i < 4; i++) {
            const int row = wm * 64 + 16 * i + (blk & 1) * 8 + rIn;
            const int kc  = (blk >> 1) * 4;
            offA[i] = (uint32_t)((row * SPAD + kc) * 4);
        }
        #pragma unroll
        for (int p = 0; p < 4; p++) {
            const int row = 256 + wn * 64 + 16 * p + (blk >> 1) * 8 + rIn;
            const int kc  = (blk & 1) * 4;
            offB[p] = (uint32_t)((row * SPAD + kc) * 4);
        }
    }

    const int NKS = K >> 3;

    auto stage = [&](int s, int ks) {
        const uint32_t sb = smemBase + (uint32_t)(s * STG_FL * 4);
        const float* ga = A + (size_t)(bm + arow) * K + ks * 8;
        cpa16(sb + (uint32_t)(arow * SPAD * 4), ga);
        cpa16(sb + (uint32_t)((arow * SPAD + 4) * 4), ga + 4);
        const float* gb = Bt + (size_t)(bn + brow) * K + ks * 8 + bhalf * 4;
        cpa16(sb + (uint32_t)(((256 + brow) * SPAD + bhalf * 4) * 4), gb);
        asm volatile("cp.async.commit_group;" ::: "memory");
    };

    float acc[4][8][4];
    #pragma unroll
    for (int i = 0; i < 4; i++)
        #pragma unroll
        for (int j = 0; j < 8; j++)
            #pragma unroll
            for (int q = 0; q < 4; q++) acc[i][j][q] = 0.f;

    #pragma unroll
    for (int s = 0; s < STAGES - 1; s++) {
        if (s < NKS) stage(s, s);
        else asm volatile("cp.async.commit_group;" ::: "memory");
    }

    int buf = 0, nxt = STAGES - 1;
    for (int ks = 0; ks < NKS; ks++) {
        asm volatile("cp.async.wait_group 3;" ::: "memory");
        __syncthreads();
        const uint32_t sb = smemBase + (uint32_t)(buf * STG_FL * 4);

        uint32_t afr[4][4], bfr[8][2];
        #pragma unroll
        for (int i = 0; i < 4; i++) ldsm4(afr[i], sb + offA[i]);
        #pragma unroll
        for (int p = 0; p < 4; p++) {
            uint32_t r[4];
            ldsm4(r, sb + offB[p]);
            bfr[2 * p][0] = r[0]; bfr[2 * p][1] = r[1];
            bfr[2 * p + 1][0] = r[2]; bfr[2 * p + 1][1] = r[3];
        }
        #pragma unroll
        for (int i = 0; i < 4; i++)
            #pragma unroll
            for (int j = 0; j < 8; j++)
                mma8(acc[i][j], afr[i], bfr[j]);

        if (ks + STAGES - 1 < NKS) stage(nxt, ks + STAGES - 1);
        else asm volatile("cp.async.commit_group;" ::: "memory");

        if (++buf == STAGES) buf = 0;
        if (++nxt == STAGES) nxt = 0;
    }

    // ---- epilogue ----
    const bool useTanh = (bn < COL_G) || (bn >= COL_XS && bn < COL_DEC);
    const int g  = lane >> 2, tg = lane & 3;
    #pragma unroll
    for (int i = 0; i < 4; i++) {
        const int r0 = bm + wm * 64 + 16 * i + g;
        #pragma unroll
        for (int j = 0; j < 8; j++) {
            const int col = bn + wn * 64 + 8 * j + 2 * tg;
            const float2 bs = *(const float2*)(bias + col);
            #pragma unroll
            for (int h = 0; h < 2; h++) {
                const int row = r0 + 8 * h;
                const float v0 = acc[i][j][2 * h]     + bs.x;
                const float v1 = acc[i][j][2 * h + 1] + bs.y;
                float2 o;
                if (EPI == 0) {
                    if (useTanh) { o.x = tanhf(v0); o.y = tanhf(v1); }
                    else {
                        o.x = 1.f / (1.f + expf(-v0));
                        o.y = 1.f / (1.f + expf(-v1));
                    }
                } else if (EPI == 1) {
                    const float2 gg = *(const float2*)(e1 + (size_t)row * lde + col);
                    const float2 uu = *(const float2*)(e2 + (size_t)row * lde + col);
                    o.x = tf32rna(gg.x * v0 + (1.f - gg.x) * uu.x);
                    o.y = tf32rna(gg.y * v1 + (1.f - gg.y) * uu.y);
                } else {
                    const float2 xx = *(const float2*)(e1 + (size_t)row * lde + col);
                    o.x = v0 + xx.x;
                    o.y = v1 + xx.y;
                }
                *(float2*)(C + (size_t)row * ldc + col) = o;
            }
        }
    }
}

// ---------------- launcher ----------------
extern "C" void kernel_launch(void* const* d_in, const int* in_sizes, int n_in,
                              void* d_out, int out_size) {
    const float* x    = (const float*)d_in[0];
    const float* ln_g = (const float*)d_in[1];
    const float* ln_b = (const float*)d_in[2];
    const float* mixw = (const float*)d_in[3];
    const float* mixb = (const float*)d_in[4];
    const float* Wi   = (const float*)d_in[5];
    const float* bi   = (const float*)d_in[6];
    const float* Wsin = (const float*)d_in[7];
    const float* bsin = (const float*)d_in[8];
    const float* Wd   = (const float*)d_in[9];
    const float* bd   = (const float*)d_in[10];
    const float* Wsel = (const float*)d_in[11];
    const float* bsel = (const float*)d_in[12];
    const float* Wso  = (const float*)d_in[13];
    const float* bso  = (const float*)d_in[14];
    const float* Wg   = (const float*)d_in[15];
    const float* bg   = (const float*)d_in[16];
    const float* Wout = (const float*)d_in[17];
    const float* bout = (const float*)d_in[18];

    float *p_h, *p_mixed, *p_mx, *p_st, *p_wT, *p_bias;
    cudaGetSymbolAddress((void**)&p_h,     g_h);
    cudaGetSymbolAddress((void**)&p_mixed, g_mixed);
    cudaGetSymbolAddress((void**)&p_mx,    g_mx);
    cudaGetSymbolAddress((void**)&p_st,    g_st);
    cudaGetSymbolAddress((void**)&p_wT,    g_wT);
    cudaGetSymbolAddress((void**)&p_bias,  g_bias);

    cudaFuncSetAttribute(mma2<0>, cudaFuncAttributeMaxDynamicSharedMemorySize, SMEM_BYTES);
    cudaFuncSetAttribute(mma2<1>, cudaFuncAttributeMaxDynamicSharedMemorySize, SMEM_BYTES);
    cudaFuncSetAttribute(mma2<2>, cudaFuncAttributeMaxDynamicSharedMemorySize, SMEM_BYTES);

    const dim3 tb(32, 8);
    auto tr = [&](const float* W, size_t off, int K, int N) {
        transpose_kernel<<<dim3(N / 32, K / 32), tb>>>(W, p_wT + off, K, N);
    };

    // 0) weight transposes into packed layout + fused bias
    tr(Wi,   OFFB_WI,   DIMn, DIMn);
    tr(Wg,   OFFB_WG,   DIMn, DIMn);
    tr(Wsin, OFFB_WSIN, DIMn, SDIMn);
    tr(Wd,   OFFB_WD,   DIMn, SDIMn);
    tr(Wsel, OFFB_WSEL, DIMn, SDIMn);
    tr(Wso,  OFF_WSO,   SDIMn, DIMn);
    tr(Wout, OFF_WOUT,  DIMn, DIMn);
    pack_bias<<<(NBIG + 255) / 256, 256>>>(bi, bg, bsin, bd, bsel);

    // 1) LayerNorm + depthwise conv (conv rounds to tf32)
    ln_kernel<<<Mn, 256>>>(x, ln_g, ln_b);
    {
        const int nf4 = Mn * DIMn / 4;
        conv_kernel<<<(nf4 + 255) / 256, 256>>>(mixw, mixb);
    }

    // 2) fused projection GEMM: [M,1024] @ [1024,2816] -> g_mx (act fused)
    mma2<0><<<dim3(NBIG / 128, Mn / 256), 256, SMEM_BYTES>>>(
        p_mixed, p_wT, p_bias, p_mx, nullptr, nullptr, DIMn, NBIG, 0);

    // 3) chunked scan; p3 writes round(sel*state) -> g_st
    scan_p1<<<dim3(NCH, Bn), SDIMn>>>();
    scan_p2<<<Bn, SDIMn>>>();
    scan_p3<<<dim3(NCH, Bn), SDIMn>>>();

    // 4) y = (sel*st)@Wso + bso, fused gate -> z (g_h, rounded)
    mma2<1><<<dim3(DIMn / 128, Mn / 256), 256, SMEM_BYTES>>>(
        p_st, p_wT + OFF_WSO, bso, p_h, p_mx + COL_G, p_mx + COL_U,
        SDIMn, DIMn, NBIG);

    // 5) out = z@Wout + bout + x
    mma2<2><<<dim3(DIMn / 128, Mn / 256), 256, SMEM_BYTES>>>(
        p_h, p_wT + OFF_WOUT, bout, (float*)d_out, x, nullptr,
        DIMn, DIMn, DIMn);
}

// round 5
// speedup vs baseline: 1.1123x; 1.1123x over previous
#include <cuda_runtime.h>
#include <cstdint>
#include <math.h>

// Problem constants
constexpr int Bn    = 4;
constexpr int Sn    = 4096;
constexpr int DIMn  = 1024;
constexpr int SDIMn = 256;
constexpr int Mn    = Bn * Sn;          // 16384 tokens
constexpr int TCH   = 32;               // scan chunk length
constexpr int NCH   = Sn / TCH;         // 128 chunks per sequence
constexpr int NBIG  = 2816;             // fused projection width

// column offsets inside the fused output [M, 2816]
constexpr int COL_U    = 0;      // tanh    (Wi)
constexpr int COL_G    = 1024;   // sigmoid (Wg)
constexpr int COL_XS   = 2048;   // tanh    (Wsin)
constexpr int COL_DEC  = 2304;   // sigmoid (Wd)
constexpr int COL_SEL  = 2560;   // sigmoid (Wsel)

// ---------------- scratch (device globals; no allocations) ----------------
__device__ __align__(16) float g_h    [(size_t)Mn * DIMn];   // LN out, later z
__device__ __align__(16) float g_mixed[(size_t)Mn * DIMn];
__device__ __align__(16) float g_mx   [(size_t)Mn * NBIG];   // fused proj out
__device__ __align__(16) float g_st   [(size_t)Mn * SDIMn];  // round(sel*state)
__device__ __align__(16) float g_chA  [Bn * NCH * SDIMn];
__device__ __align__(16) float g_chB  [Bn * NCH * SDIMn];
__device__ __align__(16) float g_chS0 [Bn * NCH * SDIMn];
__device__ __align__(16) float g_bias [NBIG];

// transposed (tf32-rounded) weights, packed [n][k]
constexpr size_t OFFB_WI   = 0;
constexpr size_t OFFB_WG   = (size_t)1024 * 1024;
constexpr size_t OFFB_WSIN = (size_t)2048 * 1024;
constexpr size_t OFFB_WD   = (size_t)2304 * 1024;
constexpr size_t OFFB_WSEL = (size_t)2560 * 1024;
constexpr size_t OFF_WSO   = (size_t)2816 * 1024;            // 1024 rows x K=256
constexpr size_t OFF_WOUT  = OFF_WSO + (size_t)1024 * 256;   // 1024 rows x K=1024
__device__ __align__(16) float g_wT[OFF_WOUT + (size_t)1024 * 1024];

// ---------------- helpers ----------------
__device__ __forceinline__ float tf32rna(float v) {
    uint32_t u;
    asm("cvt.rna.tf32.f32 %0, %1;" : "=r"(u) : "f"(v));
    return __uint_as_float(u);
}
__device__ __forceinline__ uint32_t smem_u32(const void* p) {
    uint32_t a;
    asm("{ .reg .u64 t; cvta.to.shared.u64 t, %1; cvt.u32.u64 %0, t; }"
        : "=r"(a) : "l"(p));
    return a;
}
__device__ __forceinline__ void cpa16(uint32_t s, const void* g) {
    asm volatile("cp.async.cg.shared.global [%0], [%1], 16;" :: "r"(s), "l"(g));
}
__device__ __forceinline__ void ldsm4(uint32_t* r, uint32_t addr) {
    asm volatile("ldmatrix.sync.aligned.m8n8.x4.shared.b16 {%0,%1,%2,%3}, [%4];"
                 : "=r"(r[0]), "=r"(r[1]), "=r"(r[2]), "=r"(r[3]) : "r"(addr));
}
__device__ __forceinline__ void mma8(float* d, const uint32_t* a, const uint32_t* b) {
    asm volatile(
        "mma.sync.aligned.m16n8k8.row.col.f32.tf32.tf32.f32 "
        "{%0,%1,%2,%3}, {%4,%5,%6,%7}, {%8,%9}, {%0,%1,%2,%3};"
        : "+f"(d[0]), "+f"(d[1]), "+f"(d[2]), "+f"(d[3])
        : "r"(a[0]), "r"(a[1]), "r"(a[2]), "r"(a[3]), "r"(b[0]), "r"(b[1]));
}

// ---------------- LayerNorm ----------------
__global__ void ln_kernel(const float* __restrict__ x,
                          const float* __restrict__ gw,
                          const float* __restrict__ bw) {
    const int row = blockIdx.x;
    const int t   = threadIdx.x;
    const float* xr = x + (size_t)row * DIMn;

    float4 v = *(const float4*)(xr + t * 4);
    float s  = v.x + v.y + v.z + v.w;
    float s2 = fmaf(v.x, v.x, fmaf(v.y, v.y, fmaf(v.z, v.z, v.w * v.w)));
    #pragma unroll
    for (int o = 16; o > 0; o >>= 1) {
        s  += __shfl_xor_sync(0xffffffffu, s,  o);
        s2 += __shfl_xor_sync(0xffffffffu, s2, o);
    }
    __shared__ float ws[8], ws2[8];
    __shared__ float s_mu, s_rs;
    const int warp = t >> 5, lane = t & 31;
    if (lane == 0) { ws[warp] = s; ws2[warp] = s2; }
    __syncthreads();
    if (t == 0) {
        float a = 0.f, b = 0.f;
        #pragma unroll
        for (int i = 0; i < 8; i++) { a += ws[i]; b += ws2[i]; }
        float mu  = a * (1.0f / DIMn);
        float var = b * (1.0f / DIMn) - mu * mu;
        s_mu = mu; s_rs = rsqrtf(var + 1e-5f);
    }
    __syncthreads();
    const float mu = s_mu, rs = s_rs;
    float4 g4 = *(const float4*)(gw + t * 4);
    float4 b4 = *(const float4*)(bw + t * 4);
    float4 o;
    o.x = (v.x - mu) * rs * g4.x + b4.x;
    o.y = (v.y - mu) * rs * g4.y + b4.y;
    o.z = (v.z - mu) * rs * g4.z + b4.z;
    o.w = (v.w - mu) * rs * g4.w + b4.w;
    *(float4*)(g_h + (size_t)row * DIMn + t * 4) = o;
}

// ---------------- depthwise conv1d (output tf32-rounded) ----------------
__global__ void conv_kernel(const float* __restrict__ mw,
                            const float* __restrict__ mb) {
    const int idx = blockIdx.x * blockDim.x + threadIdx.x;
    constexpr int D4 = DIMn / 4;
    if (idx >= Mn * D4) return;
    const int m = idx / D4;
    const int d = (idx - m * D4) * 4;
    const int s = m % Sn;

    const float4 c = *(const float4*)(g_h + (size_t)m * DIMn + d);
    float4 l = make_float4(0.f, 0.f, 0.f, 0.f);
    float4 r = make_float4(0.f, 0.f, 0.f, 0.f);
    if (s > 0)      l = *(const float4*)(g_h + (size_t)(m - 1) * DIMn + d);
    if (s < Sn - 1) r = *(const float4*)(g_h + (size_t)(m + 1) * DIMn + d);

    const float* lc = (const float*)&l;
    const float* cc = (const float*)&c;
    const float* rc = (const float*)&r;
    float4 out; float* oc = (float*)&out;
    #pragma unroll
    for (int j = 0; j < 4; j++) {
        const float w0 = __ldg(mw + (d + j) * 3 + 0);
        const float w1 = __ldg(mw + (d + j) * 3 + 1);
        const float w2 = __ldg(mw + (d + j) * 3 + 2);
        oc[j] = tf32rna(fmaf(w0, lc[j], fmaf(w1, cc[j],
                         fmaf(w2, rc[j], __ldg(mb + d + j)))));
    }
    *(float4*)(g_mixed + (size_t)m * DIMn + d) = out;
}

// ---------------- chunked scan (reads fused buffer g_mx) ----------------
__global__ void scan_p1() {
    const int b = blockIdx.y, c = blockIdx.x, n = threadIdx.x;
    const size_t row0 = (size_t)(b * Sn + c * TCH);
    float A = 1.f, st = 0.f;
    #pragma unroll
    for (int t = 0; t < TCH; t++) {
        const size_t rb = (row0 + t) * NBIG;
        const float d  = g_mx[rb + COL_DEC + n];
        const float xv = g_mx[rb + COL_XS  + n];
        A *= d;
        st = fmaf(d, st, (1.f - d) * xv);
    }
    const int o = (b * NCH + c) * SDIMn + n;
    g_chA[o] = A; g_chB[o] = st;
}
__global__ void scan_p2() {
    const int b = blockIdx.x, n = threadIdx.x;
    float s = 0.f;
    #pragma unroll 4
    for (int c = 0; c < NCH; c++) {
        const int o = (b * NCH + c) * SDIMn + n;
        g_chS0[o] = s;
        s = fmaf(g_chA[o], s, g_chB[o]);
    }
}
__global__ void scan_p3() {
    const int b = blockIdx.y, c = blockIdx.x, n = threadIdx.x;
    const size_t row0 = (size_t)(b * Sn + c * TCH);
    float st = g_chS0[(b * NCH + c) * SDIMn + n];
    #pragma unroll
    for (int t = 0; t < TCH; t++) {
        const size_t rb = (row0 + t) * NBIG;
        const float d  = g_mx[rb + COL_DEC + n];
        const float xv = g_mx[rb + COL_XS  + n];
        st = fmaf(d, st, (1.f - d) * xv);
        const float sl = g_mx[rb + COL_SEL + n];
        g_st[(row0 + t) * SDIMn + n] = tf32rna(sl * st);
    }
}

// ---------------- batched transposes (tf32-rounded) ----------------
// big block: 5 weights, all K=1024, tiles-per-weight = Nw
__global__ void tr_big(const float* __restrict__ Wi, const float* __restrict__ Wg,
                       const float* __restrict__ Wsin, const float* __restrict__ Wd,
                       const float* __restrict__ Wsel) {
    __shared__ float tile[32][33];
    int t = blockIdx.x;
    const float* src; float* dst; int N;
    if (t < 1024)      { src = Wi;   dst = g_wT + OFFB_WI;   N = 1024; }
    else if (t < 2048) { src = Wg;   dst = g_wT + OFFB_WG;   N = 1024; t -= 1024; }
    else if (t < 2304) { src = Wsin; dst = g_wT + OFFB_WSIN; N = 256;  t -= 2048; }
    else if (t < 2560) { src = Wd;   dst = g_wT + OFFB_WD;   N = 256;  t -= 2304; }
    else               { src = Wsel; dst = g_wT + OFFB_WSEL; N = 256;  t -= 2560; }
    const int ntx = N / 32;
    const int n0 = (t % ntx) * 32, k0 = (t / ntx) * 32;
    const int tx = threadIdx.x, ty = threadIdx.y;   // 32 x 8
    #pragma unroll
    for (int j = 0; j < 32; j += 8)
        tile[ty + j][tx] = src[(size_t)(k0 + ty + j) * N + n0 + tx];
    __syncthreads();
    #pragma unroll
    for (int j = 0; j < 32; j += 8)
        dst[(size_t)(n0 + ty + j) * 1024 + k0 + tx] = tf32rna(tile[tx][ty + j]);
}
__global__ void tr_small(const float* __restrict__ Wso, const float* __restrict__ Wout) {
    __shared__ float tile[32][33];
    int t = blockIdx.x;
    const float* src; float* dst; int K;
    if (t < 256) { src = Wso;  dst = g_wT + OFF_WSO;  K = 256; }
    else         { src = Wout; dst = g_wT + OFF_WOUT; K = 1024; t -= 256; }
    const int ntx = 1024 / 32;
    const int n0 = (t % ntx) * 32, k0 = (t / ntx) * 32;
    const int tx = threadIdx.x, ty = threadIdx.y;
    #pragma unroll
    for (int j = 0; j < 32; j += 8)
        tile[ty + j][tx] = src[(size_t)(k0 + ty + j) * 1024 + n0 + tx];
    __syncthreads();
    #pragma unroll
    for (int j = 0; j < 32; j += 8)
        dst[(size_t)(n0 + ty + j) * K + k0 + tx] = tf32rna(tile[tx][ty + j]);
}

// ---------------- pack fused bias ----------------
__global__ void pack_bias(const float* __restrict__ bi, const float* __restrict__ bg,
                          const float* __restrict__ bsin, const float* __restrict__ bd,
                          const float* __restrict__ bsel) {
    const int t = blockIdx.x * 256 + threadIdx.x;
    if (t >= NBIG) return;
    float v;
    if (t < 1024)      v = bi[t];
    else if (t < 2048) v = bg[t - 1024];
    else if (t < 2304) v = bsin[t - 2048];
    else if (t < 2560) v = bd[t - 2304];
    else               v = bsel[t - 2560];
    g_bias[t] = v;
}

// ---------------- tf32 mma GEMM (128x128, 8 warps 64x32, ldmatrix) --------
// EPI 0: per-column act (fused layout); 1: round(g*v+(1-g)*u); 2: v + x
constexpr int SPAD  = 20;                    // 16 data + 4 pad floats per row
constexpr int STG_FL = 256 * SPAD;           // A rows 0-127, B rows 128-255
constexpr int GSMEM  = 2 * STG_FL * 4;       // 40960 B per... x2 buffers = 81920

template <int EPI>
__global__ void __launch_bounds__(256, 2)
mma3(const float* __restrict__ A, const float* __restrict__ Bt,
     const float* __restrict__ bias, float* __restrict__ C,
     const float* __restrict__ e1, const float* __restrict__ e2,
     int K, int ldc, int lde) {
    extern __shared__ float smc[];
    const int tid  = threadIdx.x;
    const int wid  = tid >> 5, lane = tid & 31;
    const int wm   = wid & 1;        // 2 row groups of 64
    const int wn   = wid >> 1;       // 4 col groups of 32
    const int bm   = blockIdx.y * 128;
    const int bn   = blockIdx.x * 128;
    const uint32_t base = smem_u32(smc);

    // staging: thread -> A row tid>>1 (2 chunks), B row tid>>1 (2 chunks)
    const int srow = tid >> 1;
    const int sq   = (tid & 1) * 2;          // chunk pair 0-1 or 2-3
    auto stage = [&](int buf, int ks) {
        const uint32_t sb = base + (uint32_t)(buf * STG_FL * 4);
        const float* ga = A + (size_t)(bm + srow) * K + ks * 16 + sq * 4;
        cpa16(sb + (uint32_t)((srow * SPAD + sq * 4) * 4), ga);
        cpa16(sb + (uint32_t)((srow * SPAD + sq * 4 + 4) * 4), ga + 4);
        const float* gb = Bt + (size_t)(bn + srow) * K + ks * 16 + sq * 4;
        cpa16(sb + (uint32_t)(((128 + srow) * SPAD + sq * 4) * 4), gb);
        cpa16(sb + (uint32_t)(((128 + srow) * SPAD + sq * 4 + 4) * 4), gb + 4);
        asm volatile("cp.async.commit_group;" ::: "memory");
    };

    // ldmatrix offsets (bytes, rel. to stage base), k0=0
    uint32_t offA[4], offB[2];
    {
        const int blk = lane >> 3, rIn = lane & 7;
        #pragma unroll
        for (int i = 0; i < 4; i++) {
            const int row = wm * 64 + 16 * i + (blk & 1) * 8 + rIn;
            const int kc  = (blk >> 1) * 4;
            offA[i] = (uint32_t)((row * SPAD + kc) * 4);
        }
        #pragma unroll
        for (int p = 0; p < 2; p++) {
            const int row = 128 + wn * 32 + 16 * p + (blk >> 1) * 8 + rIn;
            const int kc  = (blk & 1) * 4;
            offB[p] = (uint32_t)((row * SPAD + kc) * 4);
        }
    }

    float acc[4][4][4];
    #pragma unroll
    for (int i = 0; i < 4; i++)
        #pragma unroll
        for (int j = 0; j < 4; j++)
            #pragma unroll
            for (int q = 0; q < 4; q++) acc[i][j][q] = 0.f;

    const int NKS = K >> 4;
    stage(0, 0);
    stage(1, 1);

    for (int ks = 0; ks < NKS; ks++) {
        if (ks + 1 < NKS) asm volatile("cp.async.wait_group 1;" ::: "memory");
        else              asm volatile("cp.async.wait_group 0;" ::: "memory");
        __syncthreads();
        const uint32_t sb = base + (uint32_t)((ks & 1) * STG_FL * 4);

        #pragma unroll
        for (int k0 = 0; k0 < 2; k0++) {
            const uint32_t kb = sb + (uint32_t)(k0 * 32);   // +8 floats
            uint32_t afr[4][4], bfr[4][2];
            #pragma unroll
            for (int i = 0; i < 4; i++) ldsm4(afr[i], kb + offA[i]);
            #pragma unroll
            for (int p = 0; p < 2; p++) {
                uint32_t r[4];
                ldsm4(r, kb + offB[p]);
                bfr[2 * p][0] = r[0];     bfr[2 * p][1] = r[1];
                bfr[2 * p + 1][0] = r[2]; bfr[2 * p + 1][1] = r[3];
            }
            #pragma unroll
            for (int i = 0; i < 4; i++)
                #pragma unroll
                for (int j = 0; j < 4; j++)
                    mma8(acc[i][j], afr[i], bfr[j]);
        }
        __syncthreads();
        if (ks + 2 < NKS) stage(ks & 1, ks + 2);
    }

    // ---- epilogue ----
    const bool useTanh = (bn < COL_G) || (bn >= COL_XS && bn < COL_DEC);
    const int g  = lane >> 2, tg = lane & 3;
    #pragma unroll
    for (int i = 0; i < 4; i++) {
        const int r0 = bm + wm * 64 + 16 * i + g;
        #pragma unroll
        for (int j = 0; j < 4; j++) {
            const int col = bn + wn * 32 + 8 * j + 2 * tg;
            const float2 bs = *(const float2*)(bias + col);
            #pragma unroll
            for (int h = 0; h < 2; h++) {
                const int row = r0 + 8 * h;
                const float v0 = acc[i][j][2 * h]     + bs.x;
                const float v1 = acc[i][j][2 * h + 1] + bs.y;
                float2 o;
                if (EPI == 0) {
                    if (useTanh) { o.x = tanhf(v0); o.y = tanhf(v1); }
                    else {
                        o.x = 1.f / (1.f + expf(-v0));
                        o.y = 1.f / (1.f + expf(-v1));
                    }
                } else if (EPI == 1) {
                    const float2 gg = *(const float2*)(e1 + (size_t)row * lde + col);
                    const float2 uu = *(const float2*)(e2 + (size_t)row * lde + col);
                    o.x = tf32rna(gg.x * v0 + (1.f - gg.x) * uu.x);
                    o.y = tf32rna(gg.y * v1 + (1.f - gg.y) * uu.y);
                } else {
                    const float2 xx = *(const float2*)(e1 + (size_t)row * lde + col);
                    o.x = v0 + xx.x;
                    o.y = v1 + xx.y;
                }
                *(float2*)(C + (size_t)row * ldc + col) = o;
            }
        }
    }
}

// ---------------- launcher ----------------
extern "C" void kernel_launch(void* const* d_in, const int* in_sizes, int n_in,
                              void* d_out, int out_size) {
    const float* x    = (const float*)d_in[0];
    const float* ln_g = (const float*)d_in[1];
    const float* ln_b = (const float*)d_in[2];
    const float* mixw = (const float*)d_in[3];
    const float* mixb = (const float*)d_in[4];
    const float* Wi   = (const float*)d_in[5];
    const float* bi   = (const float*)d_in[6];
    const float* Wsin = (const float*)d_in[7];
    const float* bsin = (const float*)d_in[8];
    const float* Wd   = (const float*)d_in[9];
    const float* bd   = (const float*)d_in[10];
    const float* Wsel = (const float*)d_in[11];
    const float* bsel = (const float*)d_in[12];
    const float* Wso  = (const float*)d_in[13];
    const float* bso  = (const float*)d_in[14];
    const float* Wg   = (const float*)d_in[15];
    const float* bg   = (const float*)d_in[16];
    const float* Wout = (const float*)d_in[17];
    const float* bout = (const float*)d_in[18];

    float *p_h, *p_mixed, *p_mx, *p_st, *p_wT, *p_bias;
    cudaGetSymbolAddress((void**)&p_h,     g_h);
    cudaGetSymbolAddress((void**)&p_mixed, g_mixed);
    cudaGetSymbolAddress((void**)&p_mx,    g_mx);
    cudaGetSymbolAddress((void**)&p_st,    g_st);
    cudaGetSymbolAddress((void**)&p_wT,    g_wT);
    cudaGetSymbolAddress((void**)&p_bias,  g_bias);

    cudaFuncSetAttribute(mma3<0>, cudaFuncAttributeMaxDynamicSharedMemorySize, GSMEM);
    cudaFuncSetAttribute(mma3<1>, cudaFuncAttributeMaxDynamicSharedMemorySize, GSMEM);
    cudaFuncSetAttribute(mma3<2>, cudaFuncAttributeMaxDynamicSharedMemorySize, GSMEM);

    const dim3 tb(32, 8);

    // launch 0-1: LN + conv
    ln_kernel<<<Mn, 256>>>(x, ln_g, ln_b);
    {
        const int nf4 = Mn * DIMn / 4;
        conv_kernel<<<(nf4 + 255) / 256, 256>>>(mixw, mixb);
    }
    // launch 2-4: transposes + bias
    tr_big<<<2816, tb>>>(Wi, Wg, Wsin, Wd, Wsel);
    tr_small<<<1280, tb>>>(Wso, Wout);
    pack_bias<<<(NBIG + 255) / 256, 256>>>(bi, bg, bsin, bd, bsel);

    // launch 5: fused projection GEMM  [M,1024] @ [1024,2816] -> g_mx
    mma3<0><<<dim3(NBIG / 128, Mn / 128), 256, GSMEM>>>(
        p_mixed, p_wT, p_bias, p_mx, nullptr, nullptr, DIMn, NBIG, 0);

    // launch 6-8: chunked scan; p3 writes round(sel*state)
    scan_p1<<<dim3(NCH, Bn), SDIMn>>>();
    scan_p2<<<Bn, SDIMn>>>();
    scan_p3<<<dim3(NCH, Bn), SDIMn>>>();

    // launch 9: y = (sel*st)@Wso + bso, fused gate -> z
    mma3<1><<<dim3(DIMn / 128, Mn / 128), 256, GSMEM>>>(
        p_st, p_wT + OFF_WSO, bso, p_h, p_mx + COL_G, p_mx + COL_U,
        SDIMn, DIMn, NBIG);

    // launch 10: out = z@Wout + bout + x
    mma3<2><<<dim3(DIMn / 128, Mn / 128), 256, GSMEM>>>(
        p_h, p_wT + OFF_WOUT, bout, (float*)d_out, x, nullptr,
        DIMn, DIMn, DIMn);
}

// round 7
// speedup vs baseline: 1.2563x; 1.1295x over previous
#include <cuda_runtime.h>
#include <cstdint>
#include <math.h>

// Problem constants
constexpr int Bn    = 4;
constexpr int Sn    = 4096;
constexpr int DIMn  = 1024;
constexpr int SDIMn = 256;
constexpr int Mn    = Bn * Sn;          // 16384 tokens
constexpr int TCH   = 32;               // scan chunk length
constexpr int NCH   = Sn / TCH;         // 128 chunks per sequence
constexpr int NBIG  = 2816;             // fused projection width

// column offsets inside the fused output [M, 2816]
constexpr int COL_U    = 0;      // tanh    (Wi)
constexpr int COL_G    = 1024;   // sigmoid (Wg)
constexpr int COL_XS   = 2048;   // tanh    (Wsin)
constexpr int COL_DEC  = 2304;   // sigmoid (Wd)
constexpr int COL_SEL  = 2560;   // sigmoid (Wsel)

// ---------------- scratch (device globals; no allocations) ----------------
__device__ __align__(16) float g_h    [(size_t)Mn * DIMn];   // LN out, later z
__device__ __align__(16) float g_mixed[(size_t)Mn * DIMn];
__device__ __align__(16) float g_mx   [(size_t)Mn * NBIG];   // fused proj out
__device__ __align__(16) float g_st   [(size_t)Mn * SDIMn];  // round(sel*state)
__device__ __align__(16) float g_chA  [Bn * NCH * SDIMn];
__device__ __align__(16) float g_chB  [Bn * NCH * SDIMn];
__device__ __align__(16) float g_chS0 [Bn * NCH * SDIMn];
__device__ __align__(16) float g_bias [NBIG];

// transposed (tf32-rounded) weights, packed [n][k]
constexpr size_t OFFB_WI   = 0;
constexpr size_t OFFB_WG   = (size_t)1024 * 1024;
constexpr size_t OFFB_WSIN = (size_t)2048 * 1024;
constexpr size_t OFFB_WD   = (size_t)2304 * 1024;
constexpr size_t OFFB_WSEL = (size_t)2560 * 1024;
constexpr size_t OFF_WSO   = (size_t)2816 * 1024;            // 1024 rows x K=256
constexpr size_t OFF_WOUT  = OFF_WSO + (size_t)1024 * 256;   // 1024 rows x K=1024
__device__ __align__(16) float g_wT[OFF_WOUT + (size_t)1024 * 1024];

// ---------------- helpers ----------------
__device__ __forceinline__ float tf32rna(float v) {
    uint32_t u;
    asm("cvt.rna.tf32.f32 %0, %1;" : "=r"(u) : "f"(v));
    return __uint_as_float(u);
}
__device__ __forceinline__ uint32_t smem_u32(const void* p) {
    uint32_t a;
    asm("{ .reg .u64 t; cvta.to.shared.u64 t, %1; cvt.u32.u64 %0, t; }"
        : "=r"(a) : "l"(p));
    return a;
}
__device__ __forceinline__ void cpa16(uint32_t s, const void* g) {
    asm volatile("cp.async.cg.shared.global [%0], [%1], 16;" :: "r"(s), "l"(g));
}
__device__ __forceinline__ void ldsm4(uint32_t* r, uint32_t addr) {
    asm volatile("ldmatrix.sync.aligned.m8n8.x4.shared.b16 {%0,%1,%2,%3}, [%4];"
                 : "=r"(r[0]), "=r"(r[1]), "=r"(r[2]), "=r"(r[3]) : "r"(addr));
}
__device__ __forceinline__ void mma8(float* d, const uint32_t* a, const uint32_t* b) {
    asm volatile(
        "mma.sync.aligned.m16n8k8.row.col.f32.tf32.tf32.f32 "
        "{%0,%1,%2,%3}, {%4,%5,%6,%7}, {%8,%9}, {%0,%1,%2,%3};"
        : "+f"(d[0]), "+f"(d[1]), "+f"(d[2]), "+f"(d[3])
        : "r"(a[0]), "r"(a[1]), "r"(a[2]), "r"(a[3]), "r"(b[0]), "r"(b[1]));
}

// ---------------- LayerNorm ----------------
__global__ void ln_kernel(const float* __restrict__ x,
                          const float* __restrict__ gw,
                          const float* __restrict__ bw) {
    const int row = blockIdx.x;
    const int t   = threadIdx.x;
    const float* xr = x + (size_t)row * DIMn;

    float4 v = *(const float4*)(xr + t * 4);
    float s  = v.x + v.y + v.z + v.w;
    float s2 = fmaf(v.x, v.x, fmaf(v.y, v.y, fmaf(v.z, v.z, v.w * v.w)));
    #pragma unroll
    for (int o = 16; o > 0; o >>= 1) {
        s  += __shfl_xor_sync(0xffffffffu, s,  o);
        s2 += __shfl_xor_sync(0xffffffffu, s2, o);
    }
    __shared__ float ws[8], ws2[8];
    __shared__ float s_mu, s_rs;
    const int warp = t >> 5, lane = t & 31;
    if (lane == 0) { ws[warp] = s; ws2[warp] = s2; }
    __syncthreads();
    if (t == 0) {
        float a = 0.f, b = 0.f;
        #pragma unroll
        for (int i = 0; i < 8; i++) { a += ws[i]; b += ws2[i]; }
        float mu  = a * (1.0f / DIMn);
        float var = b * (1.0f / DIMn) - mu * mu;
        s_mu = mu; s_rs = rsqrtf(var + 1e-5f);
    }
    __syncthreads();
    const float mu = s_mu, rs = s_rs;
    float4 g4 = *(const float4*)(gw + t * 4);
    float4 b4 = *(const float4*)(bw + t * 4);
    float4 o;
    o.x = (v.x - mu) * rs * g4.x + b4.x;
    o.y = (v.y - mu) * rs * g4.y + b4.y;
    o.z = (v.z - mu) * rs * g4.z + b4.z;
    o.w = (v.w - mu) * rs * g4.w + b4.w;
    *(float4*)(g_h + (size_t)row * DIMn + t * 4) = o;
}

// ---------------- depthwise conv1d (output tf32-rounded) ----------------
__global__ void conv_kernel(const float* __restrict__ mw,
                            const float* __restrict__ mb) {
    const int idx = blockIdx.x * blockDim.x + threadIdx.x;
    constexpr int D4 = DIMn / 4;
    if (idx >= Mn * D4) return;
    const int m = idx / D4;
    const int d = (idx - m * D4) * 4;
    const int s = m % Sn;

    const float4 c = *(const float4*)(g_h + (size_t)m * DIMn + d);
    float4 l = make_float4(0.f, 0.f, 0.f, 0.f);
    float4 r = make_float4(0.f, 0.f, 0.f, 0.f);
    if (s > 0)      l = *(const float4*)(g_h + (size_t)(m - 1) * DIMn + d);
    if (s < Sn - 1) r = *(const float4*)(g_h + (size_t)(m + 1) * DIMn + d);

    const float* lc = (const float*)&l;
    const float* cc = (const float*)&c;
    const float* rc = (const float*)&r;
    float4 out; float* oc = (float*)&out;
    #pragma unroll
    for (int j = 0; j < 4; j++) {
        const float w0 = __ldg(mw + (d + j) * 3 + 0);
        const float w1 = __ldg(mw + (d + j) * 3 + 1);
        const float w2 = __ldg(mw + (d + j) * 3 + 2);
        oc[j] = tf32rna(fmaf(w0, lc[j], fmaf(w1, cc[j],
                         fmaf(w2, rc[j], __ldg(mb + d + j)))));
    }
    *(float4*)(g_mixed + (size_t)m * DIMn + d) = out;
}

// ---------------- chunked scan (reads fused buffer g_mx) ----------------
__global__ void scan_p1() {
    const int b = blockIdx.y, c = blockIdx.x, n = threadIdx.x;
    const size_t row0 = (size_t)(b * Sn + c * TCH);
    float A = 1.f, st = 0.f;
    #pragma unroll
    for (int t = 0; t < TCH; t++) {
        const size_t rb = (row0 + t) * NBIG;
        const float d  = g_mx[rb + COL_DEC + n];
        const float xv = g_mx[rb + COL_XS  + n];
        A *= d;
        st = fmaf(d, st, (1.f - d) * xv);
    }
    const int o = (b * NCH + c) * SDIMn + n;
    g_chA[o] = A; g_chB[o] = st;
}
__global__ void scan_p2() {
    const int b = blockIdx.x, n = threadIdx.x;
    float s = 0.f;
    #pragma unroll 4
    for (int c = 0; c < NCH; c++) {
        const int o = (b * NCH + c) * SDIMn + n;
        g_chS0[o] = s;
        s = fmaf(g_chA[o], s, g_chB[o]);
    }
}
__global__ void scan_p3() {
    const int b = blockIdx.y, c = blockIdx.x, n = threadIdx.x;
    const size_t row0 = (size_t)(b * Sn + c * TCH);
    float st = g_chS0[(b * NCH + c) * SDIMn + n];
    #pragma unroll
    for (int t = 0; t < TCH; t++) {
        const size_t rb = (row0 + t) * NBIG;
        const float d  = g_mx[rb + COL_DEC + n];
        const float xv = g_mx[rb + COL_XS  + n];
        st = fmaf(d, st, (1.f - d) * xv);
        const float sl = g_mx[rb + COL_SEL + n];
        g_st[(row0 + t) * SDIMn + n] = tf32rna(sl * st);
    }
}

// ---------------- batched transposes (tf32-rounded) ----------------
__global__ void tr_big(const float* __restrict__ Wi, const float* __restrict__ Wg,
                       const float* __restrict__ Wsin, const float* __restrict__ Wd,
                       const float* __restrict__ Wsel) {
    __shared__ float tile[32][33];
    int t = blockIdx.x;
    const float* src; float* dst; int N;
    if (t < 1024)      { src = Wi;   dst = g_wT + OFFB_WI;   N = 1024; }
    else if (t < 2048) { src = Wg;   dst = g_wT + OFFB_WG;   N = 1024; t -= 1024; }
    else if (t < 2304) { src = Wsin; dst = g_wT + OFFB_WSIN; N = 256;  t -= 2048; }
    else if (t < 2560) { src = Wd;   dst = g_wT + OFFB_WD;   N = 256;  t -= 2304; }
    else               { src = Wsel; dst = g_wT + OFFB_WSEL; N = 256;  t -= 2560; }
    const int ntx = N / 32;
    const int n0 = (t % ntx) * 32, k0 = (t / ntx) * 32;
    const int tx = threadIdx.x, ty = threadIdx.y;   // 32 x 8
    #pragma unroll
    for (int j = 0; j < 32; j += 8)
        tile[ty + j][tx] = src[(size_t)(k0 + ty + j) * N + n0 + tx];
    __syncthreads();
    #pragma unroll
    for (int j = 0; j < 32; j += 8)
        dst[(size_t)(n0 + ty + j) * 1024 + k0 + tx] = tf32rna(tile[tx][ty + j]);
}
__global__ void tr_small(const float* __restrict__ Wso, const float* __restrict__ Wout) {
    __shared__ float tile[32][33];
    int t = blockIdx.x;
    const float* src; float* dst; int K;
    if (t < 256) { src = Wso;  dst = g_wT + OFF_WSO;  K = 256; }
    else         { src = Wout; dst = g_wT + OFF_WOUT; K = 1024; t -= 256; }
    const int ntx = 1024 / 32;
    const int n0 = (t % ntx) * 32, k0 = (t / ntx) * 32;
    const int tx = threadIdx.x, ty = threadIdx.y;
    #pragma unroll
    for (int j = 0; j < 32; j += 8)
        tile[ty + j][tx] = src[(size_t)(k0 + ty + j) * 1024 + n0 + tx];
    __syncthreads();
    #pragma unroll
    for (int j = 0; j < 32; j += 8)
        dst[(size_t)(n0 + ty + j) * K + k0 + tx] = tf32rna(tile[tx][ty + j]);
}

// ---------------- pack fused bias ----------------
__global__ void pack_bias(const float* __restrict__ bi, const float* __restrict__ bg,
                          const float* __restrict__ bsin, const float* __restrict__ bd,
                          const float* __restrict__ bsel) {
    const int t = blockIdx.x * 256 + threadIdx.x;
    if (t >= NBIG) return;
    float v;
    if (t < 1024)      v = bi[t];
    else if (t < 2048) v = bg[t - 1024];
    else if (t < 2304) v = bsin[t - 2048];
    else if (t < 2560) v = bd[t - 2304];
    else               v = bsel[t - 2560];
    g_bias[t] = v;
}

// ---------------- tf32 mma GEMM: 128x128 tile, 4-stage cp.async ring ------
// 8 warps of 64x32, K-chunk 16, single __syncthreads per chunk.
// EPI 0: per-column act (fused layout); 1: round(g*v+(1-g)*u); 2: v + x
constexpr int SPAD   = 20;                    // 16 data + 4 pad floats per row
constexpr int STG_FL = 256 * SPAD;            // A rows 0-127, B rows 128-255
constexpr int STAGES = 4;
constexpr int GSMEM  = STAGES * STG_FL * 4;   // 81920 B per CTA

template <int EPI>
__global__ void __launch_bounds__(256, 2)
mma3(const float* __restrict__ A, const float* __restrict__ Bt,
     const float* __restrict__ bias, float* __restrict__ C,
     const float* __restrict__ e1, const float* __restrict__ e2,
     int K, int ldc, int lde) {
    extern __shared__ float smc[];
    const int tid  = threadIdx.x;
    const int wid  = tid >> 5, lane = tid & 31;
    const int wm   = wid & 1;        // 2 row groups of 64
    const int wn   = wid >> 1;       // 4 col groups of 32
    const int bm   = blockIdx.y * 128;
    const int bn   = blockIdx.x * 128;
    const uint32_t base = smem_u32(smc);

    // staging: thread -> A row tid>>1 (2 chunks), B row tid>>1 (2 chunks)
    const int srow = tid >> 1;
    const int sq   = (tid & 1) * 2;          // chunk pair 0-1 or 2-3
    auto stage = [&](int buf, int ks) {
        const uint32_t sb = base + (uint32_t)(buf * STG_FL * 4);
        const float* ga = A + (size_t)(bm + srow) * K + ks * 16 + sq * 4;
        cpa16(sb + (uint32_t)((srow * SPAD + sq * 4) * 4), ga);
        cpa16(sb + (uint32_t)((srow * SPAD + sq * 4 + 4) * 4), ga + 4);
        const float* gb = Bt + (size_t)(bn + srow) * K + ks * 16 + sq * 4;
        cpa16(sb + (uint32_t)(((128 + srow) * SPAD + sq * 4) * 4), gb);
        cpa16(sb + (uint32_t)(((128 + srow) * SPAD + sq * 4 + 4) * 4), gb + 4);
        asm volatile("cp.async.commit_group;" ::: "memory");
    };

    // ldmatrix offsets (bytes, rel. to stage base), k0=0
    uint32_t offA[4], offB[2];
    {
        const int blk = lane >> 3, rIn = lane & 7;
        #pragma unroll
        for (int i = 0; i < 4; i++) {
            const int row = wm * 64 + 16 * i + (blk & 1) * 8 + rIn;
            const int kc  = (blk >> 1) * 4;
            offA[i] = (uint32_t)((row * SPAD + kc) * 4);
        }
        #pragma unroll
        for (int p = 0; p < 2; p++) {
            const int row = 128 + wn * 32 + 16 * p + (blk >> 1) * 8 + rIn;
            const int kc  = (blk & 1) * 4;
            offB[p] = (uint32_t)((row * SPAD + kc) * 4);
        }
    }

    float acc[4][4][4];
    #pragma unroll
    for (int i = 0; i < 4; i++)
        #pragma unroll
        for (int j = 0; j < 4; j++)
            #pragma unroll
            for (int q = 0; q < 4; q++) acc[i][j][q] = 0.f;

    const int NKS = K >> 4;

    // prologue: fill 3 stages (commit per stage)
    #pragma unroll
    for (int s = 0; s < STAGES - 1; s++) {
        if (s < NKS) stage(s, s);
        else asm volatile("cp.async.commit_group;" ::: "memory");
    }

    for (int ks = 0; ks < NKS; ks++) {
        asm volatile("cp.async.wait_group %0;" :: "n"(STAGES - 2) : "memory");
        __syncthreads();
        const uint32_t sb = base + (uint32_t)((ks & (STAGES - 1)) * STG_FL * 4);

        #pragma unroll
        for (int k0 = 0; k0 < 2; k0++) {
            const uint32_t kb = sb + (uint32_t)(k0 * 32);   // +8 floats
            uint32_t afr[4][4], bfr[4][2];
            #pragma unroll
            for (int i = 0; i < 4; i++) ldsm4(afr[i], kb + offA[i]);
            #pragma unroll
            for (int p = 0; p < 2; p++) {
                uint32_t r[4];
                ldsm4(r, kb + offB[p]);
                bfr[2 * p][0] = r[0];     bfr[2 * p][1] = r[1];
                bfr[2 * p + 1][0] = r[2]; bfr[2 * p + 1][1] = r[3];
            }
            #pragma unroll
            for (int i = 0; i < 4; i++)
                #pragma unroll
                for (int j = 0; j < 4; j++)
                    mma8(acc[i][j], afr[i], bfr[j]);
        }

        // stage next chunk into the slot consumed at iteration ks-1
        if (ks + STAGES - 1 < NKS) stage((ks + STAGES - 1) & (STAGES - 1), ks + STAGES - 1);
        else asm volatile("cp.async.commit_group;" ::: "memory");
    }

    // ---- epilogue ----
    const bool useTanh = (bn < COL_G) || (bn >= COL_XS && bn < COL_DEC);
    const int g  = lane >> 2, tg = lane & 3;
    #pragma unroll
    for (int i = 0; i < 4; i++) {
        const int r0 = bm + wm * 64 + 16 * i + g;
        #pragma unroll
        for (int j = 0; j < 4; j++) {
            const int col = bn + wn * 32 + 8 * j + 2 * tg;
            const float2 bs = *(const float2*)(bias + col);
            #pragma unroll
            for (int h = 0; h < 2; h++) {
                const int row = r0 + 8 * h;
                const float v0 = acc[i][j][2 * h]     + bs.x;
                const float v1 = acc[i][j][2 * h + 1] + bs.y;
                float2 o;
                if (EPI == 0) {
                    if (useTanh) { o.x = tanhf(v0); o.y = tanhf(v1); }
                    else {
                        o.x = 1.f / (1.f + expf(-v0));
                        o.y = 1.f / (1.f + expf(-v1));
                    }
                } else if (EPI == 1) {
                    const float2 gg = *(const float2*)(e1 + (size_t)row * lde + col);
                    const float2 uu = *(const float2*)(e2 + (size_t)row * lde + col);
                    o.x = tf32rna(gg.x * v0 + (1.f - gg.x) * uu.x);
                    o.y = tf32rna(gg.y * v1 + (1.f - gg.y) * uu.y);
                } else {
                    const float2 xx = *(const float2*)(e1 + (size_t)row * lde + col);
                    o.x = v0 + xx.x;
                    o.y = v1 + xx.y;
                }
                *(float2*)(C + (size_t)row * ldc + col) = o;
            }
        }
    }
}

// ---------------- launcher ----------------
extern "C" void kernel_launch(void* const* d_in, const int* in_sizes, int n_in,
                              void* d_out, int out_size) {
    const float* x    = (const float*)d_in[0];
    const float* ln_g = (const float*)d_in[1];
    const float* ln_b = (const float*)d_in[2];
    const float* mixw = (const float*)d_in[3];
    const float* mixb = (const float*)d_in[4];
    const float* Wi   = (const float*)d_in[5];
    const float* bi   = (const float*)d_in[6];
    const float* Wsin = (const float*)d_in[7];
    const float* bsin = (const float*)d_in[8];
    const float* Wd   = (const float*)d_in[9];
    const float* bd   = (const float*)d_in[10];
    const float* Wsel = (const float*)d_in[11];
    const float* bsel = (const float*)d_in[12];
    const float* Wso  = (const float*)d_in[13];
    const float* bso  = (const float*)d_in[14];
    const float* Wg   = (const float*)d_in[15];
    const float* bg   = (const float*)d_in[16];
    const float* Wout = (const float*)d_in[17];
    const float* bout = (const float*)d_in[18];

    float *p_h, *p_mixed, *p_mx, *p_st, *p_wT, *p_bias;
    cudaGetSymbolAddress((void**)&p_h,     g_h);
    cudaGetSymbolAddress((void**)&p_mixed, g_mixed);
    cudaGetSymbolAddress((void**)&p_mx,    g_mx);
    cudaGetSymbolAddress((void**)&p_st,    g_st);
    cudaGetSymbolAddress((void**)&p_wT,    g_wT);
    cudaGetSymbolAddress((void**)&p_bias,  g_bias);

    cudaFuncSetAttribute(mma3<0>, cudaFuncAttributeMaxDynamicSharedMemorySize, GSMEM);
    cudaFuncSetAttribute(mma3<1>, cudaFuncAttributeMaxDynamicSharedMemorySize, GSMEM);
    cudaFuncSetAttribute(mma3<2>, cudaFuncAttributeMaxDynamicSharedMemorySize, GSMEM);

    const dim3 tb(32, 8);

    // launch 0-1: LN + conv
    ln_kernel<<<Mn, 256>>>(x, ln_g, ln_b);
    {
        const int nf4 = Mn * DIMn / 4;
        conv_kernel<<<(nf4 + 255) / 256, 256>>>(mixw, mixb);
    }
    // launch 2-4: transposes + bias
    tr_big<<<2816, tb>>>(Wi, Wg, Wsin, Wd, Wsel);
    tr_small<<<1280, tb>>>(Wso, Wout);
    pack_bias<<<(NBIG + 255) / 256, 256>>>(bi, bg, bsin, bd, bsel);

    // launch 5: fused projection GEMM  [M,1024] @ [1024,2816] -> g_mx
    mma3<0><<<dim3(NBIG / 128, Mn / 128), 256, GSMEM>>>(
        p_mixed, p_wT, p_bias, p_mx, nullptr, nullptr, DIMn, NBIG, 0);

    // launch 6-8: chunked scan; p3 writes round(sel*state)
    scan_p1<<<dim3(NCH, Bn), SDIMn>>>();
    scan_p2<<<Bn, SDIMn>>>();
    scan_p3<<<dim3(NCH, Bn), SDIMn>>>();

    // launch 9: y = (sel*st)@Wso + bso, fused gate -> z
    mma3<1><<<dim3(DIMn / 128, Mn / 128), 256, GSMEM>>>(
        p_st, p_wT + OFF_WSO, bso, p_h, p_mx + COL_G, p_mx + COL_U,
        SDIMn, DIMn, NBIG);

    // launch 10: out = z@Wout + bout + x
    mma3<2><<<dim3(DIMn / 128, Mn / 128), 256, GSMEM>>>(
        p_h, p_wT + OFF_WOUT, bout, (float*)d_out, x, nullptr,
        DIMn, DIMn, DIMn);
}

// round 8
// speedup vs baseline: 2.0652x; 1.6438x over previous
#include <cuda_runtime.h>
#include <cuda_fp16.h>
#include <cstdint>
#include <math.h>

// Problem constants
constexpr int Bn    = 4;
constexpr int Sn    = 4096;
constexpr int DIMn  = 1024;
constexpr int SDIMn = 256;
constexpr int Mn    = Bn * Sn;          // 16384 tokens
constexpr int TCH   = 32;               // scan chunk length
constexpr int NCH   = Sn / TCH;         // 128 chunks per sequence
constexpr int NBIG  = 2816;             // fused projection width

// column offsets inside the fused output [M, 2816]
constexpr int COL_U    = 0;      // tanh    (Wi)
constexpr int COL_G    = 1024;   // sigmoid (Wg)
constexpr int COL_XS   = 2048;   // tanh    (Wsin)
constexpr int COL_DEC  = 2304;   // sigmoid (Wd)
constexpr int COL_SEL  = 2560;   // sigmoid (Wsel)

// ---------------- scratch (device globals; no allocations) ----------------
__device__ __align__(16) float  g_h    [(size_t)Mn * DIMn];   // LN out (fp32)
__device__ __align__(16) __half g_mixed[(size_t)Mn * DIMn];   // conv out (fp16)
__device__ __align__(16) float  g_mx   [(size_t)Mn * NBIG];   // fused proj out (fp32)
__device__ __align__(16) __half g_st   [(size_t)Mn * SDIMn];  // sel*state (fp16)
__device__ __align__(16) __half g_z    [(size_t)Mn * DIMn];   // gated z (fp16)
__device__ __align__(16) float  g_chA  [Bn * NCH * SDIMn];
__device__ __align__(16) float  g_chB  [Bn * NCH * SDIMn];
__device__ __align__(16) float  g_chS0 [Bn * NCH * SDIMn];
__device__ __align__(16) float  g_bias [NBIG];

// transposed fp16 weights, packed [n][k] (element offsets)
constexpr size_t OFFB_WI   = 0;
constexpr size_t OFFB_WG   = (size_t)1024 * 1024;
constexpr size_t OFFB_WSIN = (size_t)2048 * 1024;
constexpr size_t OFFB_WD   = (size_t)2304 * 1024;
constexpr size_t OFFB_WSEL = (size_t)2560 * 1024;
constexpr size_t OFF_WSO   = (size_t)2816 * 1024;            // 1024 rows x K=256
constexpr size_t OFF_WOUT  = OFF_WSO + (size_t)1024 * 256;   // 1024 rows x K=1024
__device__ __align__(16) __half g_wT[OFF_WOUT + (size_t)1024 * 1024];

// ---------------- helpers ----------------
__device__ __forceinline__ uint32_t smem_u32(const void* p) {
    uint32_t a;
    asm("{ .reg .u64 t; cvta.to.shared.u64 t, %1; cvt.u32.u64 %0, t; }"
        : "=r"(a) : "l"(p));
    return a;
}
__device__ __forceinline__ void cpa16(uint32_t s, const void* g) {
    asm volatile("cp.async.cg.shared.global [%0], [%1], 16;" :: "r"(s), "l"(g));
}
__device__ __forceinline__ void ldsm4(uint32_t* r, uint32_t addr) {
    asm volatile("ldmatrix.sync.aligned.m8n8.x4.shared.b16 {%0,%1,%2,%3}, [%4];"
                 : "=r"(r[0]), "=r"(r[1]), "=r"(r[2]), "=r"(r[3]) : "r"(addr));
}
__device__ __forceinline__ void mma16(float* d, const uint32_t* a, const uint32_t* b) {
    asm volatile(
        "mma.sync.aligned.m16n8k16.row.col.f32.f16.f16.f32 "
        "{%0,%1,%2,%3}, {%4,%5,%6,%7}, {%8,%9}, {%0,%1,%2,%3};"
        : "+f"(d[0]), "+f"(d[1]), "+f"(d[2]), "+f"(d[3])
        : "r"(a[0]), "r"(a[1]), "r"(a[2]), "r"(a[3]), "r"(b[0]), "r"(b[1]));
}

// ---------------- LayerNorm ----------------
__global__ void ln_kernel(const float* __restrict__ x,
                          const float* __restrict__ gw,
                          const float* __restrict__ bw) {
    const int row = blockIdx.x;
    const int t   = threadIdx.x;
    const float* xr = x + (size_t)row * DIMn;

    float4 v = *(const float4*)(xr + t * 4);
    float s  = v.x + v.y + v.z + v.w;
    float s2 = fmaf(v.x, v.x, fmaf(v.y, v.y, fmaf(v.z, v.z, v.w * v.w)));
    #pragma unroll
    for (int o = 16; o > 0; o >>= 1) {
        s  += __shfl_xor_sync(0xffffffffu, s,  o);
        s2 += __shfl_xor_sync(0xffffffffu, s2, o);
    }
    __shared__ float ws[8], ws2[8];
    __shared__ float s_mu, s_rs;
    const int warp = t >> 5, lane = t & 31;
    if (lane == 0) { ws[warp] = s; ws2[warp] = s2; }
    __syncthreads();
    if (t == 0) {
        float a = 0.f, b = 0.f;
        #pragma unroll
        for (int i = 0; i < 8; i++) { a += ws[i]; b += ws2[i]; }
        float mu  = a * (1.0f / DIMn);
        float var = b * (1.0f / DIMn) - mu * mu;
        s_mu = mu; s_rs = rsqrtf(var + 1e-5f);
    }
    __syncthreads();
    const float mu = s_mu, rs = s_rs;
    float4 g4 = *(const float4*)(gw + t * 4);
    float4 b4 = *(const float4*)(bw + t * 4);
    float4 o;
    o.x = (v.x - mu) * rs * g4.x + b4.x;
    o.y = (v.y - mu) * rs * g4.y + b4.y;
    o.z = (v.z - mu) * rs * g4.z + b4.z;
    o.w = (v.w - mu) * rs * g4.w + b4.w;
    *(float4*)(g_h + (size_t)row * DIMn + t * 4) = o;
}

// ---------------- depthwise conv1d (output fp16) ----------------
__global__ void conv_kernel(const float* __restrict__ mw,
                            const float* __restrict__ mb) {
    const int idx = blockIdx.x * blockDim.x + threadIdx.x;
    constexpr int D4 = DIMn / 4;
    if (idx >= Mn * D4) return;
    const int m = idx / D4;
    const int d = (idx - m * D4) * 4;
    const int s = m % Sn;

    const float4 c = *(const float4*)(g_h + (size_t)m * DIMn + d);
    float4 l = make_float4(0.f, 0.f, 0.f, 0.f);
    float4 r = make_float4(0.f, 0.f, 0.f, 0.f);
    if (s > 0)      l = *(const float4*)(g_h + (size_t)(m - 1) * DIMn + d);
    if (s < Sn - 1) r = *(const float4*)(g_h + (size_t)(m + 1) * DIMn + d);

    const float* lc = (const float*)&l;
    const float* cc = (const float*)&c;
    const float* rc = (const float*)&r;
    float oc[4];
    #pragma unroll
    for (int j = 0; j < 4; j++) {
        const float w0 = __ldg(mw + (d + j) * 3 + 0);
        const float w1 = __ldg(mw + (d + j) * 3 + 1);
        const float w2 = __ldg(mw + (d + j) * 3 + 2);
        oc[j] = fmaf(w0, lc[j], fmaf(w1, cc[j], fmaf(w2, rc[j], __ldg(mb + d + j))));
    }
    __half2* dst = (__half2*)(g_mixed + (size_t)m * DIMn + d);
    dst[0] = __floats2half2_rn(oc[0], oc[1]);
    dst[1] = __floats2half2_rn(oc[2], oc[3]);
}

// ---------------- chunked scan (reads fused fp32 buffer g_mx) --------------
__global__ void scan_p1() {
    const int b = blockIdx.y, c = blockIdx.x, n = threadIdx.x;
    const size_t row0 = (size_t)(b * Sn + c * TCH);
    float A = 1.f, st = 0.f;
    #pragma unroll
    for (int t = 0; t < TCH; t++) {
        const size_t rb = (row0 + t) * NBIG;
        const float d  = g_mx[rb + COL_DEC + n];
        const float xv = g_mx[rb + COL_XS  + n];
        A *= d;
        st = fmaf(d, st, (1.f - d) * xv);
    }
    const int o = (b * NCH + c) * SDIMn + n;
    g_chA[o] = A; g_chB[o] = st;
}
__global__ void scan_p2() {
    const int b = blockIdx.x, n = threadIdx.x;
    float s = 0.f;
    #pragma unroll 4
    for (int c = 0; c < NCH; c++) {
        const int o = (b * NCH + c) * SDIMn + n;
        g_chS0[o] = s;
        s = fmaf(g_chA[o], s, g_chB[o]);
    }
}
__global__ void scan_p3() {
    const int b = blockIdx.y, c = blockIdx.x, n = threadIdx.x;
    const size_t row0 = (size_t)(b * Sn + c * TCH);
    float st = g_chS0[(b * NCH + c) * SDIMn + n];
    #pragma unroll
    for (int t = 0; t < TCH; t++) {
        const size_t rb = (row0 + t) * NBIG;
        const float d  = g_mx[rb + COL_DEC + n];
        const float xv = g_mx[rb + COL_XS  + n];
        st = fmaf(d, st, (1.f - d) * xv);
        const float sl = g_mx[rb + COL_SEL + n];
        g_st[(row0 + t) * SDIMn + n] = __float2half_rn(sl * st);
    }
}

// ---------------- batched transposes (fp16 out) + fused bias pack ---------
__global__ void tr_big(const float* __restrict__ Wi, const float* __restrict__ Wg,
                       const float* __restrict__ Wsin, const float* __restrict__ Wd,
                       const float* __restrict__ Wsel,
                       const float* __restrict__ bi, const float* __restrict__ bg,
                       const float* __restrict__ bsin, const float* __restrict__ bd,
                       const float* __restrict__ bsel) {
    int t = blockIdx.x;
    if (t >= 2816) {   // bias-packing blocks
        const int i = (t - 2816) * 256 + threadIdx.y * 32 + threadIdx.x;
        if (i < NBIG) {
            float v;
            if (i < 1024)      v = bi[i];
            else if (i < 2048) v = bg[i - 1024];
            else if (i < 2304) v = bsin[i - 2048];
            else if (i < 2560) v = bd[i - 2304];
            else               v = bsel[i - 2560];
            g_bias[i] = v;
        }
        return;
    }
    __shared__ float tile[32][33];
    const float* src; __half* dst; int N;
    if (t < 1024)      { src = Wi;   dst = g_wT + OFFB_WI;   N = 1024; }
    else if (t < 2048) { src = Wg;   dst = g_wT + OFFB_WG;   N = 1024; t -= 1024; }
    else if (t < 2304) { src = Wsin; dst = g_wT + OFFB_WSIN; N = 256;  t -= 2048; }
    else if (t < 2560) { src = Wd;   dst = g_wT + OFFB_WD;   N = 256;  t -= 2304; }
    else               { src = Wsel; dst = g_wT + OFFB_WSEL; N = 256;  t -= 2560; }
    const int ntx = N / 32;
    const int n0 = (t % ntx) * 32, k0 = (t / ntx) * 32;
    const int tx = threadIdx.x, ty = threadIdx.y;   // 32 x 8
    #pragma unroll
    for (int j = 0; j < 32; j += 8)
        tile[ty + j][tx] = src[(size_t)(k0 + ty + j) * N + n0 + tx];
    __syncthreads();
    #pragma unroll
    for (int j = 0; j < 32; j += 8)
        dst[(size_t)(n0 + ty + j) * 1024 + k0 + tx] = __float2half_rn(tile[tx][ty + j]);
}
__global__ void tr_small(const float* __restrict__ Wso, const float* __restrict__ Wout) {
    __shared__ float tile[32][33];
    int t = blockIdx.x;
    const float* src; __half* dst; int K;
    if (t < 256) { src = Wso;  dst = g_wT + OFF_WSO;  K = 256; }
    else         { src = Wout; dst = g_wT + OFF_WOUT; K = 1024; t -= 256; }
    const int ntx = 1024 / 32;
    const int n0 = (t % ntx) * 32, k0 = (t / ntx) * 32;
    const int tx = threadIdx.x, ty = threadIdx.y;
    #pragma unroll
    for (int j = 0; j < 32; j += 8)
        tile[ty + j][tx] = src[(size_t)(k0 + ty + j) * 1024 + n0 + tx];
    __syncthreads();
    #pragma unroll
    for (int j = 0; j < 32; j += 8)
        dst[(size_t)(n0 + ty + j) * K + k0 + tx] = __float2half_rn(tile[tx][ty + j]);
}

// ---------------- fp16 mma GEMM: 128x128 tile, 4-stage cp.async ring ------
// 8 warps of 64x32 (m16n8k16), K-chunk 32 halves, one __syncthreads/chunk.
// EPI 0: per-column act -> fp32 C (g_mx);  1: gate -> fp16 z;  2: +x -> fp32
constexpr int HPAD   = 40;                    // halves per smem row (32 + 8 pad)
constexpr int ROWB   = HPAD * 2;              // 80 bytes
constexpr int STG_B  = 256 * ROWB;            // 20480 B (A rows 0-127, B 128-255)
constexpr int STAGES = 4;
constexpr int GSMEM  = STAGES * STG_B;        // 81920 B per CTA

template <int EPI>
__global__ void __launch_bounds__(256, 2)
mma3(const __half* __restrict__ A, const __half* __restrict__ Bt,
     const float* __restrict__ bias, void* __restrict__ Cv,
     const float* __restrict__ e1, const float* __restrict__ e2,
     int K, int ldc, int lde) {
    extern __shared__ __half smh[];
    const int tid  = threadIdx.x;
    const int wid  = tid >> 5, lane = tid & 31;
    const int wm   = wid & 1;        // 2 row groups of 64
    const int wn   = wid >> 1;       // 4 col groups of 32
    const int bm   = blockIdx.y * 128;
    const int bn   = blockIdx.x * 128;
    const uint32_t base = smem_u32(smh);

    // staging: thread -> row tid>>1, half-row (tid&1): 2 x 16B (16 halves)
    const int srow = tid >> 1;
    const int sq   = tid & 1;                    // 0: halves 0-15, 1: 16-31
    auto stage = [&](int buf, int ks) {
        const uint32_t sb = base + (uint32_t)(buf * STG_B);
        const __half* ga = A + (size_t)(bm + srow) * K + ks * 32 + sq * 16;
        cpa16(sb + (uint32_t)(srow * ROWB + sq * 32), ga);
        cpa16(sb + (uint32_t)(srow * ROWB + sq * 32 + 16), ga + 8);
        const __half* gb = Bt + (size_t)(bn + srow) * K + ks * 32 + sq * 16;
        cpa16(sb + (uint32_t)((128 + srow) * ROWB + sq * 32), gb);
        cpa16(sb + (uint32_t)((128 + srow) * ROWB + sq * 32 + 16), gb + 8);
        asm volatile("cp.async.commit_group;" ::: "memory");
    };

    // ldmatrix lane offsets (bytes, rel. to stage base, k-chunk offset 0)
    uint32_t offA[4], offB[2];
    {
        const int blk = lane >> 3, rIn = lane & 7;
        #pragma unroll
        for (int i = 0; i < 4; i++) {
            const int row = wm * 64 + 16 * i + (blk & 1) * 8 + rIn;
            const int kh  = (blk >> 1) * 8;
            offA[i] = (uint32_t)(row * ROWB + kh * 2);
        }
        #pragma unroll
        for (int p = 0; p < 2; p++) {
            const int row = 128 + wn * 32 + 16 * p + (blk >> 1) * 8 + rIn;
            const int kh  = (blk & 1) * 8;
            offB[p] = (uint32_t)(row * ROWB + kh * 2);
        }
    }

    float acc[4][4][4];
    #pragma unroll
    for (int i = 0; i < 4; i++)
        #pragma unroll
        for (int j = 0; j < 4; j++)
            #pragma unroll
            for (int q = 0; q < 4; q++) acc[i][j][q] = 0.f;

    const int NKS = K >> 5;       // K-chunks of 32 halves

    #pragma unroll
    for (int s = 0; s < STAGES - 1; s++) {
        if (s < NKS) stage(s, s);
        else asm volatile("cp.async.commit_group;" ::: "memory");
    }

    for (int ks = 0; ks < NKS; ks++) {
        asm volatile("cp.async.wait_group %0;" :: "n"(STAGES - 2) : "memory");
        __syncthreads();
        const uint32_t sb = base + (uint32_t)((ks & (STAGES - 1)) * STG_B);

        #pragma unroll
        for (int k0 = 0; k0 < 2; k0++) {           // two k16 steps
            const uint32_t kb = sb + (uint32_t)(k0 * 32);   // +16 halves
            uint32_t afr[4][4], bfr[4][2];
            #pragma unroll
            for (int i = 0; i < 4; i++) ldsm4(afr[i], kb + offA[i]);
            #pragma unroll
            for (int p = 0; p < 2; p++) {
                uint32_t r[4];
                ldsm4(r, kb + offB[p]);
                bfr[2 * p][0] = r[0];     bfr[2 * p][1] = r[1];
                bfr[2 * p + 1][0] = r[2]; bfr[2 * p + 1][1] = r[3];
            }
            #pragma unroll
            for (int i = 0; i < 4; i++)
                #pragma unroll
                for (int j = 0; j < 4; j++)
                    mma16(acc[i][j], afr[i], bfr[j]);
        }

        if (ks + STAGES - 1 < NKS)
            stage((ks + STAGES - 1) & (STAGES - 1), ks + STAGES - 1);
        else
            asm volatile("cp.async.commit_group;" ::: "memory");
    }

    // ---- epilogue ----
    const bool useTanh = (bn < COL_G) || (bn >= COL_XS && bn < COL_DEC);
    const int g  = lane >> 2, tg = lane & 3;
    #pragma unroll
    for (int i = 0; i < 4; i++) {
        const int r0 = bm + wm * 64 + 16 * i + g;
        #pragma unroll
        for (int j = 0; j < 4; j++) {
            const int col = bn + wn * 32 + 8 * j + 2 * tg;
            const float2 bs = *(const float2*)(bias + col);
            #pragma unroll
            for (int h = 0; h < 2; h++) {
                const int row = r0 + 8 * h;
                const float v0 = acc[i][j][2 * h]     + bs.x;
                const float v1 = acc[i][j][2 * h + 1] + bs.y;
                if (EPI == 0) {
                    float2 o;
                    if (useTanh) { o.x = tanhf(v0); o.y = tanhf(v1); }
                    else {
                        o.x = 1.f / (1.f + expf(-v0));
                        o.y = 1.f / (1.f + expf(-v1));
                    }
                    *(float2*)((float*)Cv + (size_t)row * ldc + col) = o;
                } else if (EPI == 1) {
                    const float2 gg = *(const float2*)(e1 + (size_t)row * lde + col);
                    const float2 uu = *(const float2*)(e2 + (size_t)row * lde + col);
                    const float z0 = gg.x * v0 + (1.f - gg.x) * uu.x;
                    const float z1 = gg.y * v1 + (1.f - gg.y) * uu.y;
                    *(__half2*)((__half*)Cv + (size_t)row * ldc + col) =
                        __floats2half2_rn(z0, z1);
                } else {
                    const float2 xx = *(const float2*)(e1 + (size_t)row * lde + col);
                    float2 o;
                    o.x = v0 + xx.x;
                    o.y = v1 + xx.y;
                    *(float2*)((float*)Cv + (size_t)row * ldc + col) = o;
                }
            }
        }
    }
}

// ---------------- launcher ----------------
extern "C" void kernel_launch(void* const* d_in, const int* in_sizes, int n_in,
                              void* d_out, int out_size) {
    const float* x    = (const float*)d_in[0];
    const float* ln_g = (const float*)d_in[1];
    const float* ln_b = (const float*)d_in[2];
    const float* mixw = (const float*)d_in[3];
    const float* mixb = (const float*)d_in[4];
    const float* Wi   = (const float*)d_in[5];
    const float* bi   = (const float*)d_in[6];
    const float* Wsin = (const float*)d_in[7];
    const float* bsin = (const float*)d_in[8];
    const float* Wd   = (const float*)d_in[9];
    const float* bd   = (const float*)d_in[10];
    const float* Wsel = (const float*)d_in[11];
    const float* bsel = (const float*)d_in[12];
    const float* Wso  = (const float*)d_in[13];
    const float* bso  = (const float*)d_in[14];
    const float* Wg   = (const float*)d_in[15];
    const float* bg   = (const float*)d_in[16];
    const float* Wout = (const float*)d_in[17];
    const float* bout = (const float*)d_in[18];

    float *p_mx, *p_bias;
    __half *p_mixed, *p_st, *p_z, *p_wT;
    cudaGetSymbolAddress((void**)&p_mixed, g_mixed);
    cudaGetSymbolAddress((void**)&p_mx,    g_mx);
    cudaGetSymbolAddress((void**)&p_st,    g_st);
    cudaGetSymbolAddress((void**)&p_z,     g_z);
    cudaGetSymbolAddress((void**)&p_wT,    g_wT);
    cudaGetSymbolAddress((void**)&p_bias,  g_bias);

    cudaFuncSetAttribute(mma3<0>, cudaFuncAttributeMaxDynamicSharedMemorySize, GSMEM);
    cudaFuncSetAttribute(mma3<1>, cudaFuncAttributeMaxDynamicSharedMemorySize, GSMEM);
    cudaFuncSetAttribute(mma3<2>, cudaFuncAttributeMaxDynamicSharedMemorySize, GSMEM);

    const dim3 tb(32, 8);

    // launch 0: LayerNorm
    ln_kernel<<<Mn, 256>>>(x, ln_g, ln_b);
    // launch 1: depthwise conv (fp16 out)
    {
        const int nf4 = Mn * DIMn / 4;
        conv_kernel<<<(nf4 + 255) / 256, 256>>>(mixw, mixb);
    }
    // launch 2: big transposes + bias pack (fused into one kernel)
    tr_big<<<2816 + 11, tb>>>(Wi, Wg, Wsin, Wd, Wsel, bi, bg, bsin, bd, bsel);

    // launch 3: fused projection GEMM [M,1024]f16 @ [1024,2816]f16 -> g_mx f32
    mma3<0><<<dim3(NBIG / 128, Mn / 128), 256, GSMEM>>>(
        p_mixed, p_wT, p_bias, p_mx, nullptr, nullptr, DIMn, NBIG, 0);

    // launch 4-6: chunked scan; p3 writes half(sel*state)
    scan_p1<<<dim3(NCH, Bn), SDIMn>>>();
    scan_p2<<<Bn, SDIMn>>>();
    scan_p3<<<dim3(NCH, Bn), SDIMn>>>();

    // launch 7: small transposes (Wso, Wout)
    tr_small<<<1280, tb>>>(Wso, Wout);

    // launch 8: y = (sel*st)@Wso + bso, fused gate -> z (fp16)
    mma3<1><<<dim3(DIMn / 128, Mn / 128), 256, GSMEM>>>(
        p_st, p_wT + OFF_WSO, bso, p_z, p_mx + COL_G, p_mx + COL_U,
        SDIMn, DIMn, NBIG);

    // launch 9: out = z@Wout + bout + x
    mma3<2><<<dim3(DIMn / 128, Mn / 128), 256, GSMEM>>>(
        p_z, p_wT + OFF_WOUT, bout, d_out, x, nullptr,
        DIMn, DIMn, DIMn);
}